// round 5
// baseline (speedup 1.0000x reference)
#include <cuda_runtime.h>
#include <cstdint>

#define T_LEN 1000
#define B_SZ  512
#define C_IN  22
#define H_SZ  64
#define G4    256
#define BC    (B_SZ * C_IN)   // 11264
#define TH    (T_LEN * H_SZ)  // 64000

typedef unsigned long long ull;

// Scratch: x transposed to [t][b][c] (45 MB static device array)
__device__ float g_xT[T_LEN * BC];

// ---------------------------------------------------------------------------
// Kernel 1: transpose x [B*C, T] -> xT [T, B*C]
// ---------------------------------------------------------------------------
__global__ void transpose_kernel(const float* __restrict__ x) {
    __shared__ float tile[32][33];
    const int tx = threadIdx.x, ty = threadIdx.y;
    const int t0 = blockIdx.x * 32;
    const int r0 = blockIdx.y * 32;
#pragma unroll
    for (int i = 0; i < 32; i += 8) {
        int t = t0 + tx, r = r0 + ty + i;
        if (t < T_LEN) tile[ty + i][tx] = x[r * T_LEN + t];
    }
    __syncthreads();
#pragma unroll
    for (int i = 0; i < 32; i += 8) {
        int t = t0 + ty + i, r = r0 + tx;
        if (t < T_LEN) g_xT[t * BC + r] = tile[tx][ty + i];
    }
}

// ---------------------------------------------------------------------------
// helpers
// ---------------------------------------------------------------------------
__device__ __forceinline__ ull pack2f(float lo, float hi) {
    ull r;
    uint32_t a = __float_as_uint(lo), b = __float_as_uint(hi);
    asm("mov.b64 %0, {%1, %2};" : "=l"(r) : "r"(a), "r"(b));
    return r;
}
__device__ __forceinline__ void ffma2(ull& d, ull a, ull b) {
    asm("fma.rn.f32x2 %0, %1, %2, %3;" : "=l"(d) : "l"(a), "l"(b), "l"(d));
}
__device__ __forceinline__ ull add2(ull a, ull b) {
    ull r;
    asm("add.rn.f32x2 %0, %1, %2;" : "=l"(r) : "l"(a), "l"(b));
    return r;
}
__device__ __forceinline__ void unpack2(ull v, float& lo, float& hi) {
    uint32_t ulo, uhi;
    asm("mov.b64 {%0, %1}, %2;" : "=r"(ulo), "=r"(uhi) : "l"(v));
    lo = __uint_as_float(ulo);
    hi = __uint_as_float(uhi);
}
__device__ __forceinline__ float tanh_fast(float x) {
    float y;
    asm("tanh.approx.f32 %0, %1;" : "=f"(y) : "f"(x));
    return y;
}

// ---------------------------------------------------------------------------
// Kernel 2: fused LSTM + FC + softmax. ONE barrier per step.
// grid = 256 CTAs (2 rows X,Y each), 256 threads.
// Thread j: gate-type gt=j&3 of hidden unit u=j>>2 (W row = gt*64+u).
// Quad lanes {4u..4u+3} hold {i,f,g,o}(u): exchange via shared + __syncwarp
// (producers and consumers are in the SAME warp). All quad threads compute
// the state update redundantly; lane gt==0 publishes h (double-buffered).
// Every thread carries one FC class (n=gt) for unit u: 1 LDG/step.
// ---------------------------------------------------------------------------
__global__ void __launch_bounds__(256, 2) lstm_fused(
    const float* __restrict__ W_ih, const float* __restrict__ W_hh,
    const float* __restrict__ b_ih, const float* __restrict__ b_hh,
    const float* __restrict__ W_fc, const float* __restrict__ b_fc,
    float* __restrict__ out)
{
    __shared__ __align__(16) ull hX[2][32], hY[2][32];   // h, pair-packed, dbl-buf
    __shared__ __align__(16) ull xXs[2][12], xYs[2][12]; // x, dbl-buf
    __shared__ __align__(16) ull g2[G4];                 // gates (rowX,rowY) packed
    __shared__ float red[2 * 4 * 64];
    __shared__ float logits_sh[2][4];

    const int j  = threadIdx.x;
    const int r0 = blockIdx.x * 2;
    const int u  = j >> 2;          // hidden unit
    const int gt = j & 3;           // gate type: 0=i 1=f 2=g 3=o
    const int wrow = gt * H_SZ + u; // row in the 4H weight matrices

    // --- pack weights for W row `wrow` (once) ---
    ull whhp[32];
    {
        const float4* wp = reinterpret_cast<const float4*>(W_hh + wrow * H_SZ);
#pragma unroll
        for (int k = 0; k < 16; k++) {
            float4 v = wp[k];
            whhp[2*k]   = pack2f(v.x, v.y);
            whhp[2*k+1] = pack2f(v.z, v.w);
        }
    }
    ull wihp[11];
    {
        const float2* wp = reinterpret_cast<const float2*>(W_ih + wrow * C_IN);
#pragma unroll
        for (int c = 0; c < 11; c++) {
            float2 v = wp[c];
            wihp[c] = pack2f(v.x, v.y);
        }
    }
    const float bias = b_ih[wrow] + b_hh[wrow];

    // nonlinearity: gt==2 (g-gate) = tanh, else sigmoid = 0.5+0.5*tanh(x/2)
    const bool  is_g   = (gt == 2);
    const float nl_pre = is_g ? 1.f : 0.5f;
    const float nl_sc  = is_g ? 1.f : 0.5f;
    const float nl_off = is_g ? 0.f : 0.5f;

    // init h buffers (both) to zero
    if (j < 64)        hX[j >> 5][j & 31] = 0ull;
    else if (j < 128)  hY[(j >> 5) & 1][j & 31] = 0ull;

    // per-thread state
    float cX = 0.f, cY = 0.f;        // cell state for unit u (replicated in quad)
    float pX = 0.f, pY = 0.f;        // FC partial for class gt, unit u
    float wf = W_fc[gt * TH + u];    // W_fc[gt][0*64+u] for t=0

    // x staging roles
    const bool isSX = (j >= 128 && j < 150);
    const bool isSY = (j >= 160 && j < 182);
    float xreg = 0.f;
    int   s_cc = 0;
    const float* s_ptr = nullptr;
    if (isSX) {
        s_cc  = j - 128;
        s_ptr = g_xT + r0 * C_IN + s_cc;
        ((float*)&xXs[0][s_cc >> 1])[s_cc & 1] = s_ptr[0];
        xreg = s_ptr[BC];
    } else if (isSY) {
        s_cc  = j - 160;
        s_ptr = g_xT + (r0 + 1) * C_IN + s_cc;
        ((float*)&xYs[0][s_cc >> 1])[s_cc & 1] = s_ptr[0];
        xreg = s_ptr[BC];
    }
    __syncthreads();

    for (int t = 0; t < T_LEN; t++) {
        const int buf = t & 1;

        // ---- gate GEMV, both rows (4 independent chains) ----
        ull aX0 = pack2f(bias, 0.f), aX1 = 0ull;
        ull aY0 = aX0,               aY1 = 0ull;
        const ulonglong2* hpX = reinterpret_cast<const ulonglong2*>(hX[buf]);
        const ulonglong2* hpY = reinterpret_cast<const ulonglong2*>(hY[buf]);
#pragma unroll
        for (int k = 0; k < 16; k++) {
            ulonglong2 hA = hpX[k];
            ulonglong2 hB = hpY[k];
            ffma2(aX0, whhp[2*k],     hA.x);
            ffma2(aY0, whhp[2*k],     hB.x);
            ffma2(aX1, whhp[2*k + 1], hA.y);
            ffma2(aY1, whhp[2*k + 1], hB.y);
        }
        const ulonglong2* xpX = reinterpret_cast<const ulonglong2*>(xXs[buf]);
        const ulonglong2* xpY = reinterpret_cast<const ulonglong2*>(xYs[buf]);
#pragma unroll
        for (int c = 0; c < 5; c++) {
            ulonglong2 xA = xpX[c];
            ulonglong2 xB = xpY[c];
            ffma2(aX0, wihp[2*c],     xA.x);
            ffma2(aY0, wihp[2*c],     xB.x);
            ffma2(aX1, wihp[2*c + 1], xA.y);
            ffma2(aY1, wihp[2*c + 1], xB.y);
        }
        ffma2(aX0, wihp[10], xXs[buf][10]);
        ffma2(aY0, wihp[10], xYs[buf][10]);

        // stage x(t+1) into alt buffers; prefetch x(t+2)
        if (isSX) {
            ((float*)&xXs[buf ^ 1][s_cc >> 1])[s_cc & 1] = xreg;
            int tn = (t + 2 < T_LEN) ? t + 2 : t;
            xreg = s_ptr[tn * BC];
        } else if (isSY) {
            ((float*)&xYs[buf ^ 1][s_cc >> 1])[s_cc & 1] = xreg;
            int tn = (t + 2 < T_LEN) ? t + 2 : t;
            xreg = s_ptr[tn * BC];
        }

        // ---- nonlinearity (parallel across all 256 threads) ----
        float eX, oX2, eY, oY2;
        unpack2(add2(aX0, aX1), eX, oX2);
        unpack2(add2(aY0, aY1), eY, oY2);
        float nX = fmaf(nl_sc, tanh_fast(nl_pre * (eX + oX2)), nl_off);
        float nY = fmaf(nl_sc, tanh_fast(nl_pre * (eY + oY2)), nl_off);
        g2[j] = pack2f(nX, nY);
        __syncwarp();     // quad exchange is warp-local

        // ---- gather i,f,g,o for unit u (both rows): 2x LDS.128 ----
        const ulonglong2* gq = reinterpret_cast<const ulonglong2*>(&g2[u << 2]);
        ulonglong2 q0 = gq[0], q1 = gq[1];
        float iX, iY, fX, fY, gX, gY, oX, oY;
        unpack2(q0.x, iX, iY);
        unpack2(q0.y, fX, fY);
        unpack2(q1.x, gX, gY);
        unpack2(q1.y, oX, oY);

        // ---- state update (redundant in quad; deterministic) ----
        cX = fmaf(fX, cX, iX * gX);
        float hXv = oX * tanh_fast(cX);
        cY = fmaf(fY, cY, iY * gY);
        float hYv = oY * tanh_fast(cY);

        // publish h(t) into the alternate buffer (one lane per quad)
        if (gt == 0) {
            ((float*)hX[buf ^ 1])[u] = hXv;
            ((float*)hY[buf ^ 1])[u] = hYv;
        }

        // ---- FC accumulation: class gt, unit u, both rows ----
        pX = fmaf(hXv, wf, pX);
        pY = fmaf(hYv, wf, pY);
        int tn = (t + 1 < T_LEN) ? t + 1 : t;
        wf = W_fc[gt * TH + tn * H_SZ + u];   // prefetch next step's weight

        __syncthreads();  // h(t) + x(t+1) visible for next step
    }

    // ---- FC reduction + softmax ----
    red[(0 * 4 + gt) * 64 + u] = pX;
    red[(1 * 4 + gt) * 64 + u] = pY;
    __syncthreads();
    if (j < 8) {
        int rr = j >> 2, nn = j & 3;
        float s = 0.f;
#pragma unroll
        for (int k = 0; k < 64; k++) s += red[(rr * 4 + nn) * 64 + k];
        logits_sh[rr][nn] = s + b_fc[nn];
    }
    __syncthreads();
    if (j < 2) {
        float l0 = logits_sh[j][0], l1 = logits_sh[j][1];
        float l2 = logits_sh[j][2], l3 = logits_sh[j][3];
        float m  = fmaxf(fmaxf(l0, l1), fmaxf(l2, l3));
        float q0 = __expf(l0 - m), q1 = __expf(l1 - m);
        float q2 = __expf(l2 - m), q3 = __expf(l3 - m);
        float inv = 1.f / (q0 + q1 + q2 + q3);
        float* o = out + (r0 + j) * 4;
        o[0] = q0 * inv; o[1] = q1 * inv; o[2] = q2 * inv; o[3] = q3 * inv;
    }
}

// ---------------------------------------------------------------------------
extern "C" void kernel_launch(void* const* d_in, const int* in_sizes, int n_in,
                              void* d_out, int out_size) {
    const float* x    = (const float*)d_in[0];
    const float* W_ih = (const float*)d_in[1];
    const float* W_hh = (const float*)d_in[2];
    const float* b_ih = (const float*)d_in[3];
    const float* b_hh = (const float*)d_in[4];
    const float* W_fc = (const float*)d_in[5];
    const float* b_fc = (const float*)d_in[6];
    float* out = (float*)d_out;

    dim3 tgrid((T_LEN + 31) / 32, BC / 32);
    dim3 tblk(32, 8);
    transpose_kernel<<<tgrid, tblk>>>(x);

    lstm_fused<<<B_SZ / 2, 256>>>(W_ih, W_hh, b_ih, b_hh, W_fc, b_fc, out);
}

// round 6
// speedup vs baseline: 1.0802x; 1.0802x over previous
#include <cuda_runtime.h>
#include <cstdint>
#include <cstddef>

#define T_LEN 1000
#define B_SZ  512
#define C_IN  22
#define H_SZ  64
#define G4    256
#define TH    (T_LEN * H_SZ)  // 64000

typedef unsigned long long ull;

__device__ ull   g_xproj[(size_t)T_LEN * 256 * 256]; // [t][rowpair][col] = (valX,valY)
__device__ float g_wfcT[TH * 4];                     // [t*64+h][class]

__device__ __forceinline__ ull pack2f(float lo, float hi) {
    ull r;
    uint32_t a = __float_as_uint(lo), b = __float_as_uint(hi);
    asm("mov.b64 %0, {%1, %2};" : "=l"(r) : "r"(a), "r"(b));
    return r;
}
__device__ __forceinline__ ull splat2(float w) {
    ull r;
    uint32_t u = __float_as_uint(w);
    asm("mov.b64 %0, {%1, %1};" : "=l"(r) : "r"(u));
    return r;
}
__device__ __forceinline__ void ffma2(ull& d, ull a, ull b) {
    asm("fma.rn.f32x2 %0, %1, %2, %3;" : "=l"(d) : "l"(a), "l"(b), "l"(d));
}
__device__ __forceinline__ ull add2(ull a, ull b) {
    ull r;
    asm("add.rn.f32x2 %0, %1, %2;" : "=l"(r) : "l"(a), "l"(b));
    return r;
}
__device__ __forceinline__ void unpack2(ull v, float& lo, float& hi) {
    uint32_t ulo, uhi;
    asm("mov.b64 {%0, %1}, %2;" : "=r"(ulo), "=r"(uhi) : "l"(v));
    lo = __uint_as_float(ulo);
    hi = __uint_as_float(uhi);
}
__device__ __forceinline__ float tanh_fast(float x) {
    float y;
    asm("tanh.approx.f32 %0, %1;" : "=f"(y) : "f"(x));
    return y;
}

// ---------------------------------------------------------------------------
// Kernel A: x_proj precompute (row-pair packed), bias included.
// grid = (256 row-pairs, 16 t-tiles of 64), block = 256 (thread = gate col).
// ---------------------------------------------------------------------------
__global__ void __launch_bounds__(256) xproj_kernel(
    const float* __restrict__ x, const float* __restrict__ W_ih,
    const float* __restrict__ b_ih, const float* __restrict__ b_hh)
{
    __shared__ __align__(16) ull xs[C_IN][64];

    const int j  = threadIdx.x;
    const int rp = blockIdx.x;
    const int t0 = blockIdx.y * 64;
    const int tlen = (t0 + 64 <= T_LEN) ? 64 : (T_LEN - t0);

    const float* xbase = x + (size_t)(2 * rp) * C_IN * T_LEN;
    for (int idx = j; idx < 2 * C_IN * 64; idx += 256) {
        int r   = idx / (C_IN * 64);
        int rem = idx - r * (C_IN * 64);
        int c   = rem >> 6;
        int tt  = rem & 63;
        float v = (tt < tlen) ? xbase[(size_t)r * C_IN * T_LEN + c * T_LEN + t0 + tt] : 0.f;
        ((float*)&xs[c][tt])[r] = v;
    }

    ull wih2[C_IN];
#pragma unroll
    for (int c = 0; c < C_IN; c++) wih2[c] = splat2(W_ih[j * C_IN + c]);
    const ull bias2 = splat2(b_ih[j] + b_hh[j]);
    __syncthreads();

    for (int tt = 0; tt < tlen; tt++) {
        ull a = bias2;
#pragma unroll
        for (int c = 0; c < C_IN; c++) ffma2(a, wih2[c], xs[c][tt]);
        g_xproj[((size_t)(t0 + tt) * 256 + rp) * 256 + j] = a;
    }
}

// ---------------------------------------------------------------------------
// Kernel B: W_fc -> [t*64+h][4] float4
// ---------------------------------------------------------------------------
__global__ void wfcT_kernel(const float* __restrict__ W_fc) {
    int i = blockIdx.x * 256 + threadIdx.x;
    if (i < TH) {
        float4 v;
        v.x = W_fc[i];
        v.y = W_fc[TH + i];
        v.z = W_fc[2 * TH + i];
        v.w = W_fc[3 * TH + i];
        ((float4*)g_wfcT)[i] = v;
    }
}

// ---------------------------------------------------------------------------
// Kernel C: fused LSTM recurrence + FC + softmax.
// ---------------------------------------------------------------------------
__global__ void __launch_bounds__(256, 2) lstm_fused(
    const float* __restrict__ W_hh, const float* __restrict__ b_fc,
    float* __restrict__ out)
{
    __shared__ __align__(16) ull hXp[32], hYp[32];
    __shared__ __align__(16) ull g2[G4];
    __shared__ float red[2 * 4 * 64];
    __shared__ float logits_sh[2][4];

    const int j  = threadIdx.x;
    const int rp = blockIdx.x;
    const int r0 = rp * 2;

    ull whhp[32];
    {
        const float4* wp = reinterpret_cast<const float4*>(W_hh + j * H_SZ);
#pragma unroll
        for (int k = 0; k < 16; k++) {
            float4 v = wp[k];
            whhp[2*k]   = pack2f(v.x, v.y);
            whhp[2*k+1] = pack2f(v.z, v.w);
        }
    }

    const bool  is_g   = ((j >> 6) == 2);
    const float nl_pre = is_g ? 1.f : 0.5f;
    const float nl_sc  = is_g ? 1.f : 0.5f;
    const float nl_off = is_g ? 0.f : 0.5f;

    if (j < 32)       hXp[j] = 0ull;
    else if (j < 64)  hYp[j - 32] = 0ull;

    const int u = j;
    float cX = 0.f, cY = 0.f;
    float pX0 = 0.f, pX1 = 0.f, pX2 = 0.f, pX3 = 0.f;
    float pY0 = 0.f, pY1 = 0.f, pY2 = 0.f, pY3 = 0.f;
    float4 wf = make_float4(0.f, 0.f, 0.f, 0.f);
    if (j < 64) wf = ((const float4*)g_wfcT)[u];

    const ull* xpp = g_xproj + (size_t)rp * 256 + j;
    ull xpv = xpp[0];
    __syncthreads();

    for (int t = 0; t < T_LEN; t++) {
        // ---- phase A: gate GEMV over h (both rows), all 256 threads ----
        ull aX0 = 0ull, aX1 = 0ull, aY0 = 0ull, aY1 = 0ull;
        const ulonglong2* hpX = reinterpret_cast<const ulonglong2*>(hXp);
        const ulonglong2* hpY = reinterpret_cast<const ulonglong2*>(hYp);
#pragma unroll
        for (int k = 0; k < 16; k++) {
            ulonglong2 hA = hpX[k];
            ulonglong2 hB = hpY[k];
            ffma2(aX0, whhp[2*k],     hA.x);
            ffma2(aY0, whhp[2*k],     hB.x);
            ffma2(aX1, whhp[2*k + 1], hA.y);
            ffma2(aY1, whhp[2*k + 1], hB.y);
        }

        ull xp_next = xpv;
        if (t + 1 < T_LEN) xp_next = xpp[(size_t)(t + 1) * 256 * 256];

        float xlo, xhi;
        unpack2(xpv, xlo, xhi);
        float eX, oX2, eY, oY2;
        unpack2(add2(aX0, aX1), eX, oX2);
        unpack2(add2(aY0, aY1), eY, oY2);
        float vX = (eX + oX2) + xlo;
        float vY = (eY + oY2) + xhi;
        float nX = fmaf(nl_sc, tanh_fast(nl_pre * vX), nl_off);
        float nY = fmaf(nl_sc, tanh_fast(nl_pre * vY), nl_off);
        g2[j] = pack2f(nX, nY);
        xpv = xp_next;
        __syncthreads();

        // ---- phase B: both rows' state update (threads 0..63) ----
        if (j < 64) {
            float iX, iY, fX, fY, gX, gY, oX, oY;
            unpack2(g2[u],       iX, iY);
            unpack2(g2[ 64 + u], fX, fY);
            unpack2(g2[128 + u], gX, gY);
            unpack2(g2[192 + u], oX, oY);
            cX = fmaf(fX, cX, iX * gX);
            cY = fmaf(fY, cY, iY * gY);
            float hXv = oX * tanh_fast(cX);
            float hYv = oY * tanh_fast(cY);
            ((float*)hXp)[u] = hXv;
            ((float*)hYp)[u] = hYv;

            pX0 = fmaf(hXv, wf.x, pX0); pX1 = fmaf(hXv, wf.y, pX1);
            pX2 = fmaf(hXv, wf.z, pX2); pX3 = fmaf(hXv, wf.w, pX3);
            pY0 = fmaf(hYv, wf.x, pY0); pY1 = fmaf(hYv, wf.y, pY1);
            pY2 = fmaf(hYv, wf.z, pY2); pY3 = fmaf(hYv, wf.w, pY3);
            int tn = (t + 1 < T_LEN) ? t + 1 : t;
            wf = ((const float4*)g_wfcT)[tn * H_SZ + u];
        }
        __syncthreads();
    }

    // ---- FC reduction + softmax ----
    if (j < 64) {
        red[(0 * 4 + 0) * 64 + u] = pX0;
        red[(0 * 4 + 1) * 64 + u] = pX1;
        red[(0 * 4 + 2) * 64 + u] = pX2;
        red[(0 * 4 + 3) * 64 + u] = pX3;
        red[(1 * 4 + 0) * 64 + u] = pY0;
        red[(1 * 4 + 1) * 64 + u] = pY1;
        red[(1 * 4 + 2) * 64 + u] = pY2;
        red[(1 * 4 + 3) * 64 + u] = pY3;
    }
    __syncthreads();
    if (j < 8) {
        int rr = j >> 2, nn = j & 3;
        float s = 0.f;
#pragma unroll
        for (int k = 0; k < 64; k++) s += red[(rr * 4 + nn) * 64 + k];
        logits_sh[rr][nn] = s + b_fc[nn];
    }
    __syncthreads();
    if (j < 2) {
        float l0 = logits_sh[j][0], l1 = logits_sh[j][1];
        float l2 = logits_sh[j][2], l3 = logits_sh[j][3];
        float m  = fmaxf(fmaxf(l0, l1), fmaxf(l2, l3));
        float q0 = __expf(l0 - m), q1 = __expf(l1 - m);
        float q2 = __expf(l2 - m), q3 = __expf(l3 - m);
        float inv = 1.f / (q0 + q1 + q2 + q3);
        float* o = out + (r0 + j) * 4;
        o[0] = q0 * inv; o[1] = q1 * inv; o[2] = q2 * inv; o[3] = q3 * inv;
    }
}

// ---------------------------------------------------------------------------
extern "C" void kernel_launch(void* const* d_in, const int* in_sizes, int n_in,
                              void* d_out, int out_size) {
    const float* x    = (const float*)d_in[0];
    const float* W_ih = (const float*)d_in[1];
    const float* W_hh = (const float*)d_in[2];
    const float* b_ih = (const float*)d_in[3];
    const float* b_hh = (const float*)d_in[4];
    const float* W_fc = (const float*)d_in[5];
    const float* b_fc = (const float*)d_in[6];
    float* out = (float*)d_out;

    xproj_kernel<<<dim3(256, 16), 256>>>(x, W_ih, b_ih, b_hh);
    wfcT_kernel<<<(TH + 255) / 256, 256>>>(W_fc);
    lstm_fused<<<256, 256>>>(W_hh, b_fc, out);
}